// round 10
// baseline (speedup 1.0000x reference)
#include <cuda_runtime.h>
#include <cuda_bf16.h>

#define BATCH 4096
#define TLEN  2048
#define DIN   5
#define H1    9
#define H2    32
#define OUTL  25

// 2*log2(e): folded into stage-1/2 weights so tanh needs no pre-multiply.
#define C2L2E 2.8853900817779268f

// Scratch for stage-1 result y = [h_f | h_b] per batch row.
__device__ float g_y[BATCH * 2 * H1];

// ---------------------------------------------------------------------------
// Stage 1: bidirectional Elman RNN over T=2048. THREAD-per-sequence: all 9
// hidden states live in this thread's registers -> no sync/SHFL/LDS on the
// serial path. 8192 threads = 256 warps = 64 blocks -> <=1 warp per SMSP, so
// each warp gets the full FFMA rt=2 pipe rate.
// State kept as r = rcp(exp(z')+1); h = 1-2r folded into recurrent weights
// and bias. x streamed in 4-step chunks of 5 x float4, double-buffered.
// ---------------------------------------------------------------------------
__global__ __launch_bounds__(128, 1) void rnn1_kernel(
    const float* __restrict__ x,
    const float* __restrict__ w_ih_f, const float* __restrict__ w_hh_f,
    const float* __restrict__ b_ih_f, const float* __restrict__ b_hh_f,
    const float* __restrict__ w_ih_b, const float* __restrict__ w_hh_b,
    const float* __restrict__ b_ih_b, const float* __restrict__ b_hh_b)
{
    const int tid = blockIdx.x * 128 + threadIdx.x;   // 0..8191
    const int dir = tid >> 12;                        // block-uniform (4096/128=32)
    const int b   = tid & (BATCH - 1);

    const float* wih_g = dir ? w_ih_b : w_ih_f;
    const float* whh_g = dir ? w_hh_b : w_hh_f;
    const float* bi_g  = dir ? b_ih_b : b_ih_f;
    const float* bh_g  = dir ? b_hh_b : b_hh_f;

    // Per-thread weight registers (scaled / folded).
    float wih[H1 * DIN];        // C2L2E * w_ih[j][d]
    float whh2[H1 * H1];        // -2*C2L2E * w_hh[j][k]
    float bz[H1];               // C2L2E * (b_ih + b_hh + sum_k w_hh[j][k])
    float r[H1];
#pragma unroll
    for (int j = 0; j < H1; j++) {
#pragma unroll
        for (int d = 0; d < DIN; d++)
            wih[j * DIN + d] = C2L2E * __ldg(wih_g + j * DIN + d);
        float wsum = 0.0f;
#pragma unroll
        for (int k = 0; k < H1; k++) {
            float w = __ldg(whh_g + j * H1 + k);
            wsum += w;
            whh2[j * H1 + k] = -2.0f * C2L2E * w;
        }
        bz[j] = C2L2E * (__ldg(bi_g + j) + __ldg(bh_g + j) + wsum);
        r[j] = 0.5f;            // h = 1-2r = 0
    }

    const float4* xq = reinterpret_cast<const float4*>(x + (size_t)b * (TLEN * DIN));
    const int q0  = dir ? (TLEN / 4 - 1) * DIN : 0;   // 2555 or 0
    const int qdq = dir ? -DIN : DIN;                 // +-5 float4 per 4-step chunk

#define LOADCHUNK(c, R) do {                                   \
        const float4* _p = xq + (q0 + (c) * qdq);              \
        R[0] = __ldg(_p + 0); R[1] = __ldg(_p + 1);            \
        R[2] = __ldg(_p + 2); R[3] = __ldg(_p + 3);            \
        R[4] = __ldg(_p + 4);                                  \
    } while (0)

    // One RNN step entirely in registers: z_j = bz + wih.x + whh2.r; r = rcp(e^z+1)
#define STEP(x0, x1, x2, x3, x4) do {                                      \
        float nr[H1];                                                      \
        _Pragma("unroll")                                                  \
        for (int j = 0; j < H1; j++) {                                     \
            float z = bz[j];                                               \
            z = fmaf(wih[j * DIN + 0], (x0), z);                           \
            z = fmaf(wih[j * DIN + 1], (x1), z);                           \
            z = fmaf(wih[j * DIN + 2], (x2), z);                           \
            z = fmaf(wih[j * DIN + 3], (x3), z);                           \
            z = fmaf(wih[j * DIN + 4], (x4), z);                           \
            _Pragma("unroll")                                              \
            for (int k = 0; k < H1; k++)                                   \
                z = fmaf(whh2[j * H1 + k], r[k], z);                       \
            float e;                                                       \
            asm("ex2.approx.f32 %0, %1;" : "=f"(e) : "f"(z));              \
            asm("rcp.approx.f32 %0, %1;" : "=f"(nr[j]) : "f"(e + 1.0f));   \
        }                                                                  \
        _Pragma("unroll")                                                  \
        for (int j = 0; j < H1; j++) r[j] = nr[j];                         \
    } while (0)

#define CHUNK_FWD(R)                                               \
        STEP(R[0].x, R[0].y, R[0].z, R[0].w, R[1].x);              \
        STEP(R[1].y, R[1].z, R[1].w, R[2].x, R[2].y);              \
        STEP(R[2].z, R[2].w, R[3].x, R[3].y, R[3].z);              \
        STEP(R[3].w, R[4].x, R[4].y, R[4].z, R[4].w);

#define CHUNK_BWD(R)                                               \
        STEP(R[3].w, R[4].x, R[4].y, R[4].z, R[4].w);              \
        STEP(R[2].z, R[2].w, R[3].x, R[3].y, R[3].z);              \
        STEP(R[1].y, R[1].z, R[1].w, R[2].x, R[2].y);              \
        STEP(R[0].x, R[0].y, R[0].z, R[0].w, R[1].x);

    float4 A[5], B[5];
    LOADCHUNK(0, A);
    const int NCHUNK = TLEN / 4;   // 512 (even)
    if (dir == 0) {
        for (int c = 0; c < NCHUNK; c += 2) {
            LOADCHUNK(c + 1, B);
            CHUNK_FWD(A);
            if (c + 2 < NCHUNK) LOADCHUNK(c + 2, A);
            CHUNK_FWD(B);
        }
    } else {
        for (int c = 0; c < NCHUNK; c += 2) {
            LOADCHUNK(c + 1, B);
            CHUNK_BWD(A);
            if (c + 2 < NCHUNK) LOADCHUNK(c + 2, A);
            CHUNK_BWD(B);
        }
    }

    float* yo = g_y + b * (2 * H1) + dir * H1;
#pragma unroll
    for (int j = 0; j < H1; j++) yo[j] = fmaf(-2.0f, r[j], 1.0f);
#undef LOADCHUNK
#undef STEP
#undef CHUNK_FWD
#undef CHUNK_BWD
}

// ---------------------------------------------------------------------------
// Stage 2: 25-step RNN (input only at t=0) + linear 32->3.  (Proven R5 code.)
// One warp per batch row; lane j owns neuron j. State r exchanged via
// double-buffered smem; lanes 0-2 each own one output channel.
// ---------------------------------------------------------------------------
__global__ __launch_bounds__(256) void rnn2_kernel(
    const float* __restrict__ w_ih2, const float* __restrict__ w_hh2,
    const float* __restrict__ b_ih2, const float* __restrict__ b_hh2,
    const float* __restrict__ w_out, const float* __restrict__ b_out,
    float* __restrict__ out)
{
    __shared__ __align__(16) float rbuf[8][2][H2];   // [warp][parity][32]

    const int gtid = blockIdx.x * blockDim.x + threadIdx.x;
    const int b  = gtid >> 5;
    const int j  = gtid & 31;
    const int wl = (threadIdx.x >> 5);

    float wh2[H2];
    float wsum = 0.0f;
#pragma unroll
    for (int k = 0; k < H2; k++) {
        float w = __ldg(w_hh2 + j * H2 + k);
        wsum += w;
        wh2[k] = -2.0f * C2L2E * w;
    }
    const float bin = C2L2E * (__ldg(b_ih2 + j) + __ldg(b_hh2 + j));
    const float bz  = bin + C2L2E * wsum;

    const int oc = (j < 3) ? j : 0;
    float wor[H2];
    float osum = 0.0f;
#pragma unroll
    for (int k = 0; k < H2; k++) {
        float w = __ldg(w_out + oc * H2 + k);
        osum += w;
        wor[k] = -2.0f * w;
    }
    const float oconst = osum + __ldg(b_out + oc);

    float* sb = &rbuf[wl][0][0];                 // parity stride = 32 floats

    // ---- Step 0: h = tanh(W_ih2 @ y + b). Broadcast y via smem.
    sb[j] = (j < 2 * H1) ? g_y[b * (2 * H1) + j] : 0.0f;
    __syncwarp();
    float r;
    {
        const float4 y0 = *reinterpret_cast<const float4*>(sb + 0);
        const float4 y1 = *reinterpret_cast<const float4*>(sb + 4);
        const float4 y2 = *reinterpret_cast<const float4*>(sb + 8);
        const float4 y3 = *reinterpret_cast<const float4*>(sb + 12);
        const float  y16 = sb[16], y17 = sb[17];
        float za = bin, zb = 0.0f;
        const float* wi = w_ih2 + j * (2 * H1);
        za = fmaf(C2L2E * __ldg(wi + 0),  y0.x, za);
        zb = fmaf(C2L2E * __ldg(wi + 1),  y0.y, zb);
        za = fmaf(C2L2E * __ldg(wi + 2),  y0.z, za);
        zb = fmaf(C2L2E * __ldg(wi + 3),  y0.w, zb);
        za = fmaf(C2L2E * __ldg(wi + 4),  y1.x, za);
        zb = fmaf(C2L2E * __ldg(wi + 5),  y1.y, zb);
        za = fmaf(C2L2E * __ldg(wi + 6),  y1.z, za);
        zb = fmaf(C2L2E * __ldg(wi + 7),  y1.w, zb);
        za = fmaf(C2L2E * __ldg(wi + 8),  y2.x, za);
        zb = fmaf(C2L2E * __ldg(wi + 9),  y2.y, zb);
        za = fmaf(C2L2E * __ldg(wi + 10), y2.z, za);
        zb = fmaf(C2L2E * __ldg(wi + 11), y2.w, zb);
        za = fmaf(C2L2E * __ldg(wi + 12), y3.x, za);
        zb = fmaf(C2L2E * __ldg(wi + 13), y3.y, zb);
        za = fmaf(C2L2E * __ldg(wi + 14), y3.z, za);
        zb = fmaf(C2L2E * __ldg(wi + 15), y3.w, zb);
        za = fmaf(C2L2E * __ldg(wi + 16), y16, za);
        zb = fmaf(C2L2E * __ldg(wi + 17), y17, zb);
        float e;
        asm("ex2.approx.f32 %0, %1;" : "=f"(e) : "f"(za + zb));
        asm("rcp.approx.f32 %0, %1;" : "=f"(r) : "f"(e + 1.0f));
    }

    float* ob = out + (size_t)b * OUTL * 3;
    int p = 0;

    for (int t = 0; t < OUTL; t++) {
        sb[p * H2 + j] = r;
        __syncwarp();
        float rv[H2];
#pragma unroll
        for (int q = 0; q < H2; q += 4) {
            const float4 v = *reinterpret_cast<const float4*>(sb + p * H2 + q);
            rv[q] = v.x; rv[q + 1] = v.y; rv[q + 2] = v.z; rv[q + 3] = v.w;
        }

        float s0 = oconst, s1 = 0.f, s2 = 0.f, s3 = 0.f;
#pragma unroll
        for (int k = 0; k < H2; k += 4) {
            s0 = fmaf(wor[k],     rv[k],     s0);
            s1 = fmaf(wor[k + 1], rv[k + 1], s1);
            s2 = fmaf(wor[k + 2], rv[k + 2], s2);
            s3 = fmaf(wor[k + 3], rv[k + 3], s3);
        }
        if (j < 3) ob[t * 3 + j] = (s0 + s1) + (s2 + s3);

        if (t < OUTL - 1) {
            float q0 = bz, q1 = 0.f, q2 = 0.f, q3 = 0.f;
#pragma unroll
            for (int k = 0; k < H2; k += 4) {
                q0 = fmaf(wh2[k],     rv[k],     q0);
                q1 = fmaf(wh2[k + 1], rv[k + 1], q1);
                q2 = fmaf(wh2[k + 2], rv[k + 2], q2);
                q3 = fmaf(wh2[k + 3], rv[k + 3], q3);
            }
            float e;
            asm("ex2.approx.f32 %0, %1;" : "=f"(e) : "f"((q0 + q1) + (q2 + q3)));
            asm("rcp.approx.f32 %0, %1;" : "=f"(r) : "f"(e + 1.0f));
        }
        p ^= 1;
    }
}

extern "C" void kernel_launch(void* const* d_in, const int* in_sizes, int n_in,
                              void* d_out, int out_size)
{
    const float* x      = (const float*)d_in[0];
    const float* w_ih_f = (const float*)d_in[1];
    const float* w_hh_f = (const float*)d_in[2];
    const float* b_ih_f = (const float*)d_in[3];
    const float* b_hh_f = (const float*)d_in[4];
    const float* w_ih_b = (const float*)d_in[5];
    const float* w_hh_b = (const float*)d_in[6];
    const float* b_ih_b = (const float*)d_in[7];
    const float* b_hh_b = (const float*)d_in[8];
    const float* w_ih2  = (const float*)d_in[9];
    const float* w_hh2  = (const float*)d_in[10];
    const float* b_ih2  = (const float*)d_in[11];
    const float* b_hh2  = (const float*)d_in[12];
    const float* w_out  = (const float*)d_in[13];
    const float* b_out  = (const float*)d_in[14];
    float* out = (float*)d_out;

    // Stage 1: thread per sequence. 8192 threads = 64 blocks x 128
    // -> one block per SM, <=1 warp per SMSP.
    rnn1_kernel<<<(2 * BATCH) / 128, 128>>>(x, w_ih_f, w_hh_f, b_ih_f, b_hh_f,
                                            w_ih_b, w_hh_b, b_ih_b, b_hh_b);

    // Stage 2: warp per batch row.
    rnn2_kernel<<<(BATCH * 32) / 256, 256>>>(w_ih2, w_hh2, b_ih2, b_hh2,
                                             w_out, b_out, out);
}